// round 6
// baseline (speedup 1.0000x reference)
#include <cuda_runtime.h>
#include <cuda_bf16.h>

// Haar DWT2: input (8,32,512,512) f32 -> output (8,4,32,256,256) f32
// Subbands: LL, LH, HL, HH (pywt order: LH = highpass along H)
//
// R2: 8 output cols per thread (16 input cols), streaming cache hints.
//   Loads : 2 rows x 4 float4 = 8x LDG.E.128.CS (front-batched, MLP=8)
//   Stores: 4 subbands x 2 float4 = 8x STG.E.128.CS (1KB/warp/subband burst)

#define H_IN  512
#define W_IN  512
#define H_OUT 256
#define W_OUT 256
#define C_DIM 32
#define B_DIM 8
#define COLS_PER_THREAD 8                          // output cols per thread
#define GROUPS_PER_ROW (W_OUT / COLS_PER_THREAD)   // 32

__global__ __launch_bounds__(256) void haar_dwt2_kernel(
    const float* __restrict__ in, float* __restrict__ out)
{
    unsigned t = blockIdx.x * blockDim.x + threadIdx.x;
    // total = B*C * H_OUT * GROUPS_PER_ROW = 8*32*256*32 = 2,097,152
    unsigned j8 = t & (GROUPS_PER_ROW - 1);          // 0..31
    unsigned i  = (t >> 5) & (H_OUT - 1);            // 0..255
    unsigned bc = t >> 13;                           // 0..255  (b*32 + c)

    const float4* __restrict__ row0 = reinterpret_cast<const float4*>(
        in + ((size_t)bc * H_IN + 2u * i) * W_IN + 16u * j8);
    const float4* __restrict__ row1 = reinterpret_cast<const float4*>(
        in + ((size_t)bc * H_IN + 2u * i + 1u) * W_IN + 16u * j8);

    // front-batch all 8 loads, evict-first (read-once stream)
    float4 a0 = __ldcs(row0 + 0);
    float4 a1 = __ldcs(row0 + 1);
    float4 a2 = __ldcs(row0 + 2);
    float4 a3 = __ldcs(row0 + 3);
    float4 b0 = __ldcs(row1 + 0);
    float4 b1 = __ldcs(row1 + 1);
    float4 b2 = __ldcs(row1 + 2);
    float4 b3 = __ldcs(row1 + 3);

    float r0[16] = {a0.x,a0.y,a0.z,a0.w, a1.x,a1.y,a1.z,a1.w,
                    a2.x,a2.y,a2.z,a2.w, a3.x,a3.y,a3.z,a3.w};
    float r1[16] = {b0.x,b0.y,b0.z,b0.w, b1.x,b1.y,b1.z,b1.w,
                    b2.x,b2.y,b2.z,b2.w, b3.x,b3.y,b3.z,b3.w};

    float ll[8], lh[8], hl[8], hh[8];
#pragma unroll
    for (int k = 0; k < 8; k++) {
        float x00 = r0[2*k], x01 = r0[2*k+1];
        float x10 = r1[2*k], x11 = r1[2*k+1];
        float s0 = x00 + x01, s1 = x10 + x11;
        float d0 = x00 - x01, d1 = x10 - x11;
        ll[k] = (s0 + s1) * 0.5f;
        lh[k] = (s0 - s1) * 0.5f;
        hl[k] = (d0 + d1) * 0.5f;
        hh[k] = (d0 - d1) * 0.5f;
    }

    // output: [B, 4, C, 256, 256]
    unsigned b = bc >> 5;
    unsigned c = bc & 31;
    size_t plane = (size_t)H_OUT * W_OUT;                    // 65536
    size_t base  = (((size_t)b * 4) * C_DIM + c) * plane
                 + (size_t)i * W_OUT + 8u * j8;
    size_t sub_stride = (size_t)C_DIM * plane;

    float4* oLL = reinterpret_cast<float4*>(out + base);
    float4* oLH = reinterpret_cast<float4*>(out + base + sub_stride);
    float4* oHL = reinterpret_cast<float4*>(out + base + 2 * sub_stride);
    float4* oHH = reinterpret_cast<float4*>(out + base + 3 * sub_stride);

    __stcs(oLL + 0, make_float4(ll[0], ll[1], ll[2], ll[3]));
    __stcs(oLL + 1, make_float4(ll[4], ll[5], ll[6], ll[7]));
    __stcs(oLH + 0, make_float4(lh[0], lh[1], lh[2], lh[3]));
    __stcs(oLH + 1, make_float4(lh[4], lh[5], lh[6], lh[7]));
    __stcs(oHL + 0, make_float4(hl[0], hl[1], hl[2], hl[3]));
    __stcs(oHL + 1, make_float4(hl[4], hl[5], hl[6], hl[7]));
    __stcs(oHH + 0, make_float4(hh[0], hh[1], hh[2], hh[3]));
    __stcs(oHH + 1, make_float4(hh[4], hh[5], hh[6], hh[7]));
}

extern "C" void kernel_launch(void* const* d_in, const int* in_sizes, int n_in,
                              void* d_out, int out_size)
{
    const float* in = (const float*)d_in[0];
    float* out = (float*)d_out;
    unsigned total = B_DIM * C_DIM * H_OUT * GROUPS_PER_ROW;  // 2,097,152
    dim3 block(256);
    dim3 grid(total / 256);
    haar_dwt2_kernel<<<grid, block>>>(in, out);
}

// round 8
// speedup vs baseline: 1.1253x; 1.1253x over previous
#include <cuda_runtime.h>
#include <cuda_bf16.h>

// Haar DWT2: input (8,32,512,512) f32 -> output (8,4,32,256,256) f32
// Subbands: LL, LH, HL, HH (pywt order: LH = highpass along H)
//
// R7: back to R1 geometry (4 output cols/thread, 29 regs, occ ~74%) which
// measured 81.4% DRAM; add ONLY streaming cache hints (ldcs/stcs) on top.
//   Loads : 2 rows x 2 float4 = 4x LDG.E.128.CS (front-batched, MLP=4)
//   Stores: 4 subbands x 1 float4 = 4x STG.E.128.CS (512B/warp/subband burst)

#define H_IN  512
#define W_IN  512
#define H_OUT 256
#define W_OUT 256
#define C_DIM 32
#define B_DIM 8
#define COLS_PER_THREAD 4                          // output cols per thread
#define GROUPS_PER_ROW (W_OUT / COLS_PER_THREAD)   // 64

__global__ __launch_bounds__(256) void haar_dwt2_kernel(
    const float* __restrict__ in, float* __restrict__ out)
{
    unsigned t = blockIdx.x * blockDim.x + threadIdx.x;
    // total = B*C * H_OUT * GROUPS_PER_ROW = 8*32*256*64 = 4,194,304
    unsigned j4 = t & (GROUPS_PER_ROW - 1);          // 0..63
    unsigned i  = (t >> 6) & (H_OUT - 1);            // 0..255
    unsigned bc = t >> 14;                           // 0..255  (b*32 + c)

    const float4* __restrict__ row0 = reinterpret_cast<const float4*>(
        in + ((size_t)bc * H_IN + 2u * i) * W_IN + 8u * j4);
    const float4* __restrict__ row1 = reinterpret_cast<const float4*>(
        in + ((size_t)bc * H_IN + 2u * i + 1u) * W_IN + 8u * j4);

    // front-batch all 4 loads (MLP=4), evict-first: read-once stream
    float4 a0 = __ldcs(row0 + 0);
    float4 a1 = __ldcs(row0 + 1);
    float4 b0 = __ldcs(row1 + 0);
    float4 b1 = __ldcs(row1 + 1);

    float r0[8] = {a0.x, a0.y, a0.z, a0.w, a1.x, a1.y, a1.z, a1.w};
    float r1[8] = {b0.x, b0.y, b0.z, b0.w, b1.x, b1.y, b1.z, b1.w};

    float ll[4], lh[4], hl[4], hh[4];
#pragma unroll
    for (int k = 0; k < 4; k++) {
        float x00 = r0[2*k], x01 = r0[2*k+1];
        float x10 = r1[2*k], x11 = r1[2*k+1];
        float s0 = x00 + x01, s1 = x10 + x11;   // row sums
        float d0 = x00 - x01, d1 = x10 - x11;   // row diffs
        ll[k] = (s0 + s1) * 0.5f;
        lh[k] = (s0 - s1) * 0.5f;
        hl[k] = (d0 + d1) * 0.5f;
        hh[k] = (d0 - d1) * 0.5f;
    }

    // output: [B, 4, C, 256, 256]
    unsigned b = bc >> 5;
    unsigned c = bc & 31;
    size_t plane = (size_t)H_OUT * W_OUT;                    // 65536
    size_t base  = (((size_t)b * 4) * C_DIM + c) * plane
                 + (size_t)i * W_OUT + 4u * j4;
    size_t sub_stride = (size_t)C_DIM * plane;

    float4* oLL = reinterpret_cast<float4*>(out + base);
    float4* oLH = reinterpret_cast<float4*>(out + base + sub_stride);
    float4* oHL = reinterpret_cast<float4*>(out + base + 2 * sub_stride);
    float4* oHH = reinterpret_cast<float4*>(out + base + 3 * sub_stride);

    __stcs(oLL, make_float4(ll[0], ll[1], ll[2], ll[3]));
    __stcs(oLH, make_float4(lh[0], lh[1], lh[2], lh[3]));
    __stcs(oHL, make_float4(hl[0], hl[1], hl[2], hl[3]));
    __stcs(oHH, make_float4(hh[0], hh[1], hh[2], hh[3]));
}

extern "C" void kernel_launch(void* const* d_in, const int* in_sizes, int n_in,
                              void* d_out, int out_size)
{
    const float* in = (const float*)d_in[0];
    float* out = (float*)d_out;
    unsigned total = B_DIM * C_DIM * H_OUT * GROUPS_PER_ROW;  // 4,194,304
    dim3 block(256);
    dim3 grid(total / 256);
    haar_dwt2_kernel<<<grid, block>>>(in, out);
}